// round 14
// baseline (speedup 1.0000x reference)
#include <cuda_runtime.h>
#include <math.h>

#define NN      1023
#define NLEAVES 512
#define HD      300
#define GP      320          // padded per-gate width
#define NBP     960          // 3 * GP = 15 * 64
#define NBLK    296          // 2 blocks/SM
#define NTHR    256
#define GSTRIDE (512 * NBP)  // per-split-chunk partial buffer stride
#define MAXSP   10
#define NSHARD  32           // barrier shards
// shard s receives blocks {b : b % 32 == s}: 10 blocks for s<8, 9 for s>=8
#define SHSIZE(s) (9u + ((unsigned)(s) < 8u ? 1u : 0u))

typedef unsigned long long ull;

// ---------------- static device scratch ----------------
__device__ float g_Wxp[HD * NBP];        // packed W_ix|W_fx|W_ux
__device__ float g_Whp[HD * NBP];        // packed W_ih|W_fh|W_uh
__device__ float g_bsum[NBP];            // b_*x + b_*h
__device__ float g_XX[NN * NBP];         // x @ Wxp
__device__ float g_Gs[MAXSP * GSTRIDE];  // split-K partial child GEMM results
__device__ float g_h[NN * HD];
__device__ float g_c[NN * HD];
__device__ float g_loss[NN];
__device__ float g_logp_scratch[NN * 5];
__device__ unsigned g_cnt[NSHARD * 32];  // sharded cumulative arrival counters (128B apart)
__device__ unsigned g_rel[NSHARD * 32];  // sharded release copies (128B apart)

// ---------------- f32x2 helpers ----------------
static __device__ __forceinline__ ull pack2(float x, float y) {
    ull r;
    asm("mov.b64 %0, {%1, %2};" : "=l"(r) : "f"(x), "f"(y));
    return r;
}
static __device__ __forceinline__ void unpack2(ull v, float &x, float &y) {
    asm("mov.b64 {%0, %1}, %2;" : "=f"(x), "=f"(y) : "l"(v));
}
static __device__ __forceinline__ void ffma2(ull &d, ull a, ull b) {
    asm("fma.rn.f32x2 %0, %1, %2, %0;" : "+l"(d) : "l"(a), "l"(b));
}
// fast sigmoid / tanh: MUFU-based, rel err ~1e-6 (budget 1e-3)
static __device__ __forceinline__ float sigf(float x) {
    return __fdividef(1.0f, 1.0f + __expf(-x));
}
static __device__ __forceinline__ float tanhf_fast(float x) {
    float e = __expf(-2.0f * x);
    return __fdividef(1.0f - e, 1.0f + e);
}

// ---------------- sharded grid barrier, NSHARD=32 ----------------
static __device__ __forceinline__ void gbar(unsigned target) {
    __syncthreads();
    if (threadIdx.x == 0) {
        __threadfence();                       // release this block's writes
        atomicAdd(&g_cnt[(blockIdx.x & (NSHARD - 1)) << 5], 1u);
    }
    if (blockIdx.x == 0) {
        if (threadIdx.x < NSHARD) {
            const unsigned want = SHSIZE(threadIdx.x) * target;   // cumulative
            while (*((volatile unsigned*)&g_cnt[threadIdx.x << 5]) < want) { }
        }
        __syncthreads();
        if (threadIdx.x == 0) __threadfence();      // acquire all blocks' data
        __syncthreads();
        if (threadIdx.x < NSHARD)
            *((volatile unsigned*)&g_rel[threadIdx.x << 5]) = target;
    } else {
        if (threadIdx.x == 0) {
            const unsigned sh = (blockIdx.x & (NSHARD - 1)) << 5;
            while (*((volatile unsigned*)&g_rel[sh]) < target) { }
            __threadfence();                        // acquire (L1 invalidate)
        }
    }
    __syncthreads();
}

// ---------------- pack weights into [300][960] gate-padded strips ----------------
__global__ void pack_w(const float* __restrict__ Wix, const float* __restrict__ Wfx,
                       const float* __restrict__ Wux, const float* __restrict__ Wih,
                       const float* __restrict__ Wfh, const float* __restrict__ Wuh,
                       const float* __restrict__ bix, const float* __restrict__ bfx,
                       const float* __restrict__ bux, const float* __restrict__ bih,
                       const float* __restrict__ bfh, const float* __restrict__ buh)
{
    int idx = blockIdx.x * blockDim.x + threadIdx.x;
    if (idx < HD * NBP) {
        int k = idx / NBP, c = idx % NBP;
        int g = c / GP, j = c % GP;
        float vx = 0.f, vh = 0.f;
        if (j < HD) {
            const float* wx = (g == 0) ? Wix : (g == 1) ? Wfx : Wux;
            const float* wh = (g == 0) ? Wih : (g == 1) ? Wfh : Wuh;
            vx = wx[k * HD + j];
            vh = wh[k * HD + j];
        }
        g_Wxp[idx] = vx;
        g_Whp[idx] = vh;
    }
    if (idx < NBP) {
        int g = idx / GP, j = idx % GP;
        float v = 0.f;
        if (j < HD) {
            const float* bx = (g == 0) ? bix : (g == 1) ? bfx : bux;
            const float* bh = (g == 0) ? bih : (g == 1) ? bfh : buh;
            v = bx[j] + bh[j];
        }
        g_bsum[idx] = v;
    }
}

// ---------------- stage loader (gmem -> regs), 119us baseline ----------------
static __device__ __forceinline__ void ld_stage_regs(
    const float* __restrict__ aptr, bool aval,
    const float* __restrict__ bptr, int kb, int akq, int bk,
    float4 &a0, float4 &a1, float4 &b0, float4 &b1)
{
    const float4 z = make_float4(0.f, 0.f, 0.f, 0.f);
    int gk0 = kb + (akq << 2), gk1 = gk0 + 16;
    a0 = (aval && gk0 < HD) ? *(const float4*)(aptr + gk0) : z;
    a1 = (aval && gk1 < HD) ? *(const float4*)(aptr + gk1) : z;
    int gb0 = kb + bk, gb1 = gb0 + 16;
    b0 = (gb0 < HD) ? *(const float4*)(bptr + (size_t)gb0 * NBP) : z;
    b1 = (gb1 < HD) ? *(const float4*)(bptr + (size_t)gb1 * NBP) : z;
}

// ---------------- tiled gathered GEMM with split-K (exact 119us structure) --------
__device__ __noinline__ void gemm_stage(const float* __restrict__ src,
                                        const int* __restrict__ rowIdx, int M,
                                        const float* __restrict__ B,
                                        float* __restrict__ out, int sp, int ostride,
                                        float (&As)[2][32][68],
                                        float (&Bs)[2][32][64])
{
    const int tid = threadIdx.x;
    const int tx = tid & 15, ty = tid >> 4;
    const int am  = tid & 63;
    const int akq = tid >> 6;        // 0..3
    const int bn4 = (tid & 15) << 2;
    const int bk  = tid >> 4;        // 0..15

    const int ntm = (M + 63) >> 6;
    const int ntiles = ntm * 15 * sp;
    const int S = 10;                // stages of BK=32 over K=300

    for (int t = blockIdx.x; t < ntiles; t += NBLK) {
        const int c  = t % sp;
        const int tt = t / sp;
        const int m0 = (tt / 15) << 6;
        const int n0 = (tt % 15) << 6;
        const int s0 = (c * S) / sp;
        const int s1 = ((c + 1) * S) / sp;

        const bool aval = (m0 + am < M);
        const int  arow = aval ? rowIdx[m0 + am] : 0;
        const float* __restrict__ aptr = src + (size_t)arow * HD;
        const float* __restrict__ bptr = B + n0 + bn4;

        const bool act = (m0 + (ty << 2) < M);

        float4 a0, a1, b0, b1;
        ld_stage_regs(aptr, aval, bptr, s0 << 5, akq, bk, a0, a1, b0, b1);
        {
            int ka = akq << 2;
            As[0][ka + 0][am] = a0.x; As[0][ka + 1][am] = a0.y;
            As[0][ka + 2][am] = a0.z; As[0][ka + 3][am] = a0.w;
            As[0][16 + ka + 0][am] = a1.x; As[0][16 + ka + 1][am] = a1.y;
            As[0][16 + ka + 2][am] = a1.z; As[0][16 + ka + 3][am] = a1.w;
            *(float4*)&Bs[0][bk][bn4]      = b0;
            *(float4*)&Bs[0][bk + 16][bn4] = b1;
        }
        __syncthreads();

        ull acc[4][2];
#pragma unroll
        for (int i = 0; i < 4; i++) { acc[i][0] = pack2(0.f, 0.f); acc[i][1] = pack2(0.f, 0.f); }

        for (int s = s0; s < s1; s++) {
            const int p = (s - s0) & 1;

            if (s + 1 < s1)
                ld_stage_regs(aptr, aval, bptr, (s + 1) << 5, akq, bk, a0, a1, b0, b1);

            if (act) {
                float4 a_c = *(const float4*)&As[p][0][ty << 2];
                ulonglong2 b_c = *(const ulonglong2*)&Bs[p][0][tx << 2];
#pragma unroll
                for (int k = 0; k < 32; k++) {
                    float4 a_n;
                    ulonglong2 b_n;
                    if (k < 31) {
                        a_n = *(const float4*)&As[p][k + 1][ty << 2];
                        b_n = *(const ulonglong2*)&Bs[p][k + 1][tx << 2];
                    } else {
                        a_n = make_float4(0.f, 0.f, 0.f, 0.f);
                        b_n.x = 0; b_n.y = 0;
                    }
                    ull ap;
                    ap = pack2(a_c.x, a_c.x); ffma2(acc[0][0], ap, b_c.x); ffma2(acc[0][1], ap, b_c.y);
                    ap = pack2(a_c.y, a_c.y); ffma2(acc[1][0], ap, b_c.x); ffma2(acc[1][1], ap, b_c.y);
                    ap = pack2(a_c.z, a_c.z); ffma2(acc[2][0], ap, b_c.x); ffma2(acc[2][1], ap, b_c.y);
                    ap = pack2(a_c.w, a_c.w); ffma2(acc[3][0], ap, b_c.x); ffma2(acc[3][1], ap, b_c.y);
                    a_c = a_n; b_c = b_n;
                }
            }

            if (s + 1 < s1) {
                const int q = p ^ 1;
                int ka = akq << 2;
                As[q][ka + 0][am] = a0.x; As[q][ka + 1][am] = a0.y;
                As[q][ka + 2][am] = a0.z; As[q][ka + 3][am] = a0.w;
                As[q][16 + ka + 0][am] = a1.x; As[q][16 + ka + 1][am] = a1.y;
                As[q][16 + ka + 2][am] = a1.z; As[q][16 + ka + 3][am] = a1.w;
                *(float4*)&Bs[q][bk][bn4]      = b0;
                *(float4*)&Bs[q][bk + 16][bn4] = b1;
            }
            __syncthreads();
        }

        if (act) {
            float* __restrict__ ob = out + (size_t)c * ostride;
#pragma unroll
            for (int i = 0; i < 4; i++) {
                int gm = m0 + (ty << 2) + i;
                if (gm < M) {
                    float x0, x1, x2, x3;
                    unpack2(acc[i][0], x0, x1);
                    unpack2(acc[i][1], x2, x3);
                    *(float4*)&ob[(size_t)gm * NBP + n0 + (tx << 2)] =
                        make_float4(x0, x1, x2, x3);
                }
            }
        }
    }
}

// ---------------- level epilogue, compile-time SP (R11 winner) ----------------
template <int SP>
static __device__ __forceinline__ void level_epi(int base, int W,
                                                 const int* __restrict__ children)
{
    for (int idx = blockIdx.x * NTHR + threadIdx.x; idx < W * HD; idx += NBLK * NTHR) {
        int p = idx / HD, j = idx % HD;
        int t = base + p;
        const float* xx = g_XX + (size_t)t * NBP;
        float s_i = 0.f, s_u = 0.f, g0f = 0.f, g1f = 0.f;
#pragma unroll
        for (int c = 0; c < SP; c++) {
            const float* G0 = g_Gs + (size_t)c * GSTRIDE + (size_t)(2 * p) * NBP;
            const float* G1 = G0 + NBP;
            s_i += G0[j] + G1[j];
            g0f += G0[GP + j];
            g1f += G1[GP + j];
            s_u += G0[2 * GP + j] + G1[2 * GP + j];
        }
        float xi = xx[j]          + g_bsum[j];
        float xf = xx[GP + j]     + g_bsum[GP + j];
        float xu = xx[2 * GP + j] + g_bsum[2 * GP + j];
        float i = sigf(xi + s_i);
        float o = sigf(xf + g0f + g1f);
        float u = sigf(xu + s_u);
        float f0 = sigf(xf + g0f);
        float f1 = sigf(xf + g1f);
        int c0 = children[2 * t], c1 = children[2 * t + 1];
        float cc = i * u + f0 * g_c[c0 * HD + j] + f1 * g_c[c1 * HD + j];
        g_c[t * HD + j] = cc;
        g_h[t * HD + j] = o * tanhf_fast(cc);
    }
}

// ---------------- persistent mega-kernel ----------------
__global__ __launch_bounds__(NTHR, 2) void mega_kernel(
    const int* __restrict__ word_ids, const int* __restrict__ labels,
    const int* __restrict__ children, const float* __restrict__ emb,
    const float* __restrict__ Wout, const float* __restrict__ bout,
    float* __restrict__ out, int out_size)
{
    __shared__ float As[2][32][68];
    __shared__ __align__(16) float Bs[2][32][64];
    __shared__ float sred[NTHR];

    unsigned barno = 0;

    // ---- stage 1: prologue GEMM  XX = emb[word_ids] @ Wxp ----
    gemm_stage(emb, word_ids, NN, g_Wxp, g_XX, 1, 0, As, Bs);
    gbar(++barno);

    // ---- stage 2: leaves ----
    for (int idx = blockIdx.x * NTHR + threadIdx.x; idx < NLEAVES * HD; idx += NBLK * NTHR) {
        int t = idx / HD, j = idx % HD;
        const float* xx = g_XX + (size_t)t * NBP;
        float i = sigf(xx[j]          + g_bsum[j]);
        float o = sigf(xx[GP + j]     + g_bsum[GP + j]);
        float u = sigf(xx[2 * GP + j] + g_bsum[2 * GP + j]);
        float c = i * u;
        g_c[t * HD + j] = c;
        g_h[t * HD + j] = o * tanhf_fast(c);
    }
    gbar(++barno);

    // ---- stage 3: 9 sequential levels (split-K GEMM + unrolled epilogue) ----
    const int bases[9]  = {512, 768, 896, 960, 992, 1008, 1016, 1020, 1022};
    const int widths[9] = {256, 128, 64, 32, 16, 8, 4, 2, 1};
    const int splits[9] = {2, 4, 5, 10, 10, 10, 10, 10, 10};
#pragma unroll 1
    for (int l = 0; l < 9; l++) {
        const int W = widths[l], base = bases[l], sp = splits[l];
        gemm_stage(g_h, children + 2 * base, 2 * W, g_Whp, g_Gs, sp, GSTRIDE, As, Bs);
        gbar(++barno);
        switch (sp) {
            case 2:  level_epi<2>(base, W, children);  break;
            case 4:  level_epi<4>(base, W, children);  break;
            case 5:  level_epi<5>(base, W, children);  break;
            default: level_epi<10>(base, W, children); break;
        }
        gbar(++barno);
    }

    // ---- stage 4: logits + log_softmax + per-node loss (warp per node) ----
    {
        int gw = (blockIdx.x * NTHR + threadIdx.x) >> 5;
        int lane = threadIdx.x & 31;
        if (gw < NN) {
            const float* h = g_h + (size_t)gw * HD;
            float a0 = 0.f, a1 = 0.f, a2 = 0.f, a3 = 0.f, a4 = 0.f;
            for (int j = lane; j < HD; j += 32) {
                float hv = h[j];
                const float* w = Wout + j * 5;
                a0 += hv * w[0]; a1 += hv * w[1]; a2 += hv * w[2];
                a3 += hv * w[3]; a4 += hv * w[4];
            }
#pragma unroll
            for (int off = 16; off > 0; off >>= 1) {
                a0 += __shfl_down_sync(0xffffffffu, a0, off);
                a1 += __shfl_down_sync(0xffffffffu, a1, off);
                a2 += __shfl_down_sync(0xffffffffu, a2, off);
                a3 += __shfl_down_sync(0xffffffffu, a3, off);
                a4 += __shfl_down_sync(0xffffffffu, a4, off);
            }
            if (lane == 0) {
                float lg[5] = {a0 + bout[0], a1 + bout[1], a2 + bout[2],
                               a3 + bout[3], a4 + bout[4]};
                float mx = lg[0];
#pragma unroll
                for (int l = 1; l < 5; l++) mx = fmaxf(mx, lg[l]);
                float se = 0.f;
#pragma unroll
                for (int l = 0; l < 5; l++) se += __expf(lg[l] - mx);
                float lse = mx + __logf(se);
                float* dst = (out_size >= NN * 5) ? (out + (size_t)gw * 5)
                                                  : (g_logp_scratch + (size_t)gw * 5);
#pragma unroll
                for (int l = 0; l < 5; l++) dst[l] = lg[l] - lse;
                g_loss[gw] = -(lg[labels[gw]] - lse);
            }
        }
    }

    // ---- final barrier: arrival-only; block 0 reduces loss and resets state ----
    {
        const unsigned fin = ++barno;
        __syncthreads();
        if (threadIdx.x == 0) {
            __threadfence();
            atomicAdd(&g_cnt[(blockIdx.x & (NSHARD - 1)) << 5], 1u);
        }
        if (blockIdx.x != 0) return;

        if (threadIdx.x < NSHARD) {
            const unsigned want = SHSIZE(threadIdx.x) * fin;
            while (*((volatile unsigned*)&g_cnt[threadIdx.x << 5]) < want) { }
        }
        __syncthreads();
        if (threadIdx.x == 0) __threadfence();   // acquire: fresh g_loss
        __syncthreads();

        float v = 0.f;
        for (int i = threadIdx.x; i < NN; i += NTHR) v += g_loss[i];
        sred[threadIdx.x] = v;
        __syncthreads();
        for (int st = NTHR / 2; st > 0; st >>= 1) {
            if (threadIdx.x < st) sred[threadIdx.x] += sred[threadIdx.x + st];
            __syncthreads();
        }
        if (threadIdx.x == 0) {
            if (out_size > NN * 5)      out[NN * 5] = sred[0];
            else if (out_size < NN * 5) out[0]      = sred[0];
        }
        __syncthreads();

        // reset barrier state for the next graph replay
        if (threadIdx.x < NSHARD) {
            *((volatile unsigned*)&g_cnt[threadIdx.x << 5]) = 0;
            *((volatile unsigned*)&g_rel[threadIdx.x << 5]) = 0;
        }
        if (threadIdx.x == 0) __threadfence();
    }
}

// ---------------- launch ----------------
extern "C" void kernel_launch(void* const* d_in, const int* in_sizes, int n_in,
                              void* d_out, int out_size)
{
    const int*   word_ids = (const int*)d_in[0];
    const int*   labels   = (const int*)d_in[1];
    const int*   children = (const int*)d_in[2];
    const float* emb = (const float*)d_in[4];
    const float* Wix = (const float*)d_in[5],  *bix = (const float*)d_in[6];
    const float* Wih = (const float*)d_in[7],  *bih = (const float*)d_in[8];
    const float* Wfx = (const float*)d_in[9],  *bfx = (const float*)d_in[10];
    const float* Wfh = (const float*)d_in[11], *bfh = (const float*)d_in[12];
    const float* Wux = (const float*)d_in[13], *bux = (const float*)d_in[14];
    const float* Wuh = (const float*)d_in[15], *buh = (const float*)d_in[16];
    const float* Wout = (const float*)d_in[17], *bout = (const float*)d_in[18];
    float* out = (float*)d_out;

    pack_w<<<(HD * NBP + 255) / 256, 256>>>(Wix, Wfx, Wux, Wih, Wfh, Wuh,
                                            bix, bfx, bux, bih, bfh, buh);
    mega_kernel<<<NBLK, NTHR>>>(word_ids, labels, children, emb, Wout, bout,
                                out, out_size);
}

// round 15
// speedup vs baseline: 1.1421x; 1.1421x over previous
#include <cuda_runtime.h>
#include <math.h>

#define NN      1023
#define NLEAVES 512
#define HD      300
#define GP      320          // padded per-gate width
#define NBP     960          // 3 * GP = 15 * 64
#define NBLK    296          // 2 blocks/SM
#define NTHR    256
#define GSTRIDE (512 * NBP)  // per-split-chunk partial buffer stride
#define MAXSP   10
#define NSHARD  8            // barrier shards (NBLK % NSHARD == 0)
#define SHBLK   (NBLK / NSHARD)

typedef unsigned long long ull;

// ---------------- static device scratch ----------------
__device__ float g_Wxp[HD * NBP];        // packed W_ix|W_fx|W_ux
__device__ float g_Whp[HD * NBP];        // packed W_ih|W_fh|W_uh
__device__ float g_bsum[NBP];            // b_*x + b_*h
__device__ float g_XX[NN * NBP];         // x @ Wxp
__device__ float g_Gs[MAXSP * GSTRIDE];  // split-K partial child GEMM results
__device__ float g_h[NN * HD];
__device__ float g_c[NN * HD];
__device__ float g_loss[NN];
__device__ float g_logp_scratch[NN * 5];
__device__ unsigned g_cnt[NSHARD * 32];  // sharded cumulative arrival counters (128B apart)

// ---------------- f32x2 helpers ----------------
static __device__ __forceinline__ ull pack2(float x, float y) {
    ull r;
    asm("mov.b64 %0, {%1, %2};" : "=l"(r) : "f"(x), "f"(y));
    return r;
}
static __device__ __forceinline__ void unpack2(ull v, float &x, float &y) {
    asm("mov.b64 {%0, %1}, %2;" : "=f"(x), "=f"(y) : "l"(v));
}
static __device__ __forceinline__ void ffma2(ull &d, ull a, ull b) {
    asm("fma.rn.f32x2 %0, %1, %2, %0;" : "+l"(d) : "l"(a), "l"(b));
}
// fast sigmoid / tanh: MUFU-based, rel err ~1e-6 (budget 1e-3)
static __device__ __forceinline__ float sigf(float x) {
    return __fdividef(1.0f, 1.0f + __expf(-x));
}
static __device__ __forceinline__ float tanhf_fast(float x) {
    float e = __expf(-2.0f * x);
    return __fdividef(1.0f - e, 1.0f + e);
}

// ---------------- one-hop sharded grid barrier ----------------
// Arrive: atomicAdd on 1 of 8 shard counters (37 RMWs/line).
// Wait: EVERY block's threads 0..7 poll all 8 cumulative counters directly.
// No block0 release hop: last arrive is visible to spinners in one L2 trip.
static __device__ __forceinline__ void gbar(unsigned target) {
    __syncthreads();
    if (threadIdx.x == 0) {
        __threadfence();                       // release this block's writes
        atomicAdd(&g_cnt[(blockIdx.x & (NSHARD - 1)) << 5], 1u);
    }
    if (threadIdx.x < NSHARD) {
        const unsigned want = SHBLK * target;   // cumulative
        while (*((volatile unsigned*)&g_cnt[threadIdx.x << 5]) < want) { }
    }
    __syncthreads();
    if (threadIdx.x == 0) __threadfence();      // acquire (L1 invalidate)
    __syncthreads();
}

// ---------------- pack weights into [300][960] gate-padded strips ----------------
__global__ void pack_w(const float* __restrict__ Wix, const float* __restrict__ Wfx,
                       const float* __restrict__ Wux, const float* __restrict__ Wih,
                       const float* __restrict__ Wfh, const float* __restrict__ Wuh,
                       const float* __restrict__ bix, const float* __restrict__ bfx,
                       const float* __restrict__ bux, const float* __restrict__ bih,
                       const float* __restrict__ bfh, const float* __restrict__ buh)
{
    int idx = blockIdx.x * blockDim.x + threadIdx.x;
    if (idx < HD * NBP) {
        int k = idx / NBP, c = idx % NBP;
        int g = c / GP, j = c % GP;
        float vx = 0.f, vh = 0.f;
        if (j < HD) {
            const float* wx = (g == 0) ? Wix : (g == 1) ? Wfx : Wux;
            const float* wh = (g == 0) ? Wih : (g == 1) ? Wfh : Wuh;
            vx = wx[k * HD + j];
            vh = wh[k * HD + j];
        }
        g_Wxp[idx] = vx;
        g_Whp[idx] = vh;
    }
    if (idx < NBP) {
        int g = idx / GP, j = idx % GP;
        float v = 0.f;
        if (j < HD) {
            const float* bx = (g == 0) ? bix : (g == 1) ? bfx : bux;
            const float* bh = (g == 0) ? bih : (g == 1) ? bfh : buh;
            v = bx[j] + bh[j];
        }
        g_bsum[idx] = v;
    }
}

// ---------------- stage loader (gmem -> regs), 119us baseline ----------------
static __device__ __forceinline__ void ld_stage_regs(
    const float* __restrict__ aptr, bool aval,
    const float* __restrict__ bptr, int kb, int akq, int bk,
    float4 &a0, float4 &a1, float4 &b0, float4 &b1)
{
    const float4 z = make_float4(0.f, 0.f, 0.f, 0.f);
    int gk0 = kb + (akq << 2), gk1 = gk0 + 16;
    a0 = (aval && gk0 < HD) ? *(const float4*)(aptr + gk0) : z;
    a1 = (aval && gk1 < HD) ? *(const float4*)(aptr + gk1) : z;
    int gb0 = kb + bk, gb1 = gb0 + 16;
    b0 = (gb0 < HD) ? *(const float4*)(bptr + (size_t)gb0 * NBP) : z;
    b1 = (gb1 < HD) ? *(const float4*)(bptr + (size_t)gb1 * NBP) : z;
}

// ---------------- tiled gathered GEMM with split-K (exact 119us structure) --------
__device__ __noinline__ void gemm_stage(const float* __restrict__ src,
                                        const int* __restrict__ rowIdx, int M,
                                        const float* __restrict__ B,
                                        float* __restrict__ out, int sp, int ostride,
                                        float (&As)[2][32][68],
                                        float (&Bs)[2][32][64])
{
    const int tid = threadIdx.x;
    const int tx = tid & 15, ty = tid >> 4;
    const int am  = tid & 63;
    const int akq = tid >> 6;        // 0..3
    const int bn4 = (tid & 15) << 2;
    const int bk  = tid >> 4;        // 0..15

    const int ntm = (M + 63) >> 6;
    const int ntiles = ntm * 15 * sp;
    const int S = 10;                // stages of BK=32 over K=300

    for (int t = blockIdx.x; t < ntiles; t += NBLK) {
        const int c  = t % sp;
        const int tt = t / sp;
        const int m0 = (tt / 15) << 6;
        const int n0 = (tt % 15) << 6;
        const int s0 = (c * S) / sp;
        const int s1 = ((c + 1) * S) / sp;

        const bool aval = (m0 + am < M);
        const int  arow = aval ? rowIdx[m0 + am] : 0;
        const float* __restrict__ aptr = src + (size_t)arow * HD;
        const float* __restrict__ bptr = B + n0 + bn4;

        const bool act = (m0 + (ty << 2) < M);

        float4 a0, a1, b0, b1;
        ld_stage_regs(aptr, aval, bptr, s0 << 5, akq, bk, a0, a1, b0, b1);
        {
            int ka = akq << 2;
            As[0][ka + 0][am] = a0.x; As[0][ka + 1][am] = a0.y;
            As[0][ka + 2][am] = a0.z; As[0][ka + 3][am] = a0.w;
            As[0][16 + ka + 0][am] = a1.x; As[0][16 + ka + 1][am] = a1.y;
            As[0][16 + ka + 2][am] = a1.z; As[0][16 + ka + 3][am] = a1.w;
            *(float4*)&Bs[0][bk][bn4]      = b0;
            *(float4*)&Bs[0][bk + 16][bn4] = b1;
        }
        __syncthreads();

        ull acc[4][2];
#pragma unroll
        for (int i = 0; i < 4; i++) { acc[i][0] = pack2(0.f, 0.f); acc[i][1] = pack2(0.f, 0.f); }

        for (int s = s0; s < s1; s++) {
            const int p = (s - s0) & 1;

            if (s + 1 < s1)
                ld_stage_regs(aptr, aval, bptr, (s + 1) << 5, akq, bk, a0, a1, b0, b1);

            if (act) {
                float4 a_c = *(const float4*)&As[p][0][ty << 2];
                ulonglong2 b_c = *(const ulonglong2*)&Bs[p][0][tx << 2];
#pragma unroll
                for (int k = 0; k < 32; k++) {
                    float4 a_n;
                    ulonglong2 b_n;
                    if (k < 31) {
                        a_n = *(const float4*)&As[p][k + 1][ty << 2];
                        b_n = *(const ulonglong2*)&Bs[p][k + 1][tx << 2];
                    } else {
                        a_n = make_float4(0.f, 0.f, 0.f, 0.f);
                        b_n.x = 0; b_n.y = 0;
                    }
                    ull ap;
                    ap = pack2(a_c.x, a_c.x); ffma2(acc[0][0], ap, b_c.x); ffma2(acc[0][1], ap, b_c.y);
                    ap = pack2(a_c.y, a_c.y); ffma2(acc[1][0], ap, b_c.x); ffma2(acc[1][1], ap, b_c.y);
                    ap = pack2(a_c.z, a_c.z); ffma2(acc[2][0], ap, b_c.x); ffma2(acc[2][1], ap, b_c.y);
                    ap = pack2(a_c.w, a_c.w); ffma2(acc[3][0], ap, b_c.x); ffma2(acc[3][1], ap, b_c.y);
                    a_c = a_n; b_c = b_n;
                }
            }

            if (s + 1 < s1) {
                const int q = p ^ 1;
                int ka = akq << 2;
                As[q][ka + 0][am] = a0.x; As[q][ka + 1][am] = a0.y;
                As[q][ka + 2][am] = a0.z; As[q][ka + 3][am] = a0.w;
                As[q][16 + ka + 0][am] = a1.x; As[q][16 + ka + 1][am] = a1.y;
                As[q][16 + ka + 2][am] = a1.z; As[q][16 + ka + 3][am] = a1.w;
                *(float4*)&Bs[q][bk][bn4]      = b0;
                *(float4*)&Bs[q][bk + 16][bn4] = b1;
            }
            __syncthreads();
        }

        if (act) {
            float* __restrict__ ob = out + (size_t)c * ostride;
#pragma unroll
            for (int i = 0; i < 4; i++) {
                int gm = m0 + (ty << 2) + i;
                if (gm < M) {
                    float x0, x1, x2, x3;
                    unpack2(acc[i][0], x0, x1);
                    unpack2(acc[i][1], x2, x3);
                    *(float4*)&ob[(size_t)gm * NBP + n0 + (tx << 2)] =
                        make_float4(x0, x1, x2, x3);
                }
            }
        }
    }
}

// ---------------- level epilogue, compile-time SP (R11 winner) ----------------
template <int SP>
static __device__ __forceinline__ void level_epi(int base, int W,
                                                 const int* __restrict__ children)
{
    for (int idx = blockIdx.x * NTHR + threadIdx.x; idx < W * HD; idx += NBLK * NTHR) {
        int p = idx / HD, j = idx % HD;
        int t = base + p;
        const float* xx = g_XX + (size_t)t * NBP;
        float s_i = 0.f, s_u = 0.f, g0f = 0.f, g1f = 0.f;
#pragma unroll
        for (int c = 0; c < SP; c++) {
            const float* G0 = g_Gs + (size_t)c * GSTRIDE + (size_t)(2 * p) * NBP;
            const float* G1 = G0 + NBP;
            s_i += G0[j] + G1[j];
            g0f += G0[GP + j];
            g1f += G1[GP + j];
            s_u += G0[2 * GP + j] + G1[2 * GP + j];
        }
        float xi = xx[j]          + g_bsum[j];
        float xf = xx[GP + j]     + g_bsum[GP + j];
        float xu = xx[2 * GP + j] + g_bsum[2 * GP + j];
        float i = sigf(xi + s_i);
        float o = sigf(xf + g0f + g1f);
        float u = sigf(xu + s_u);
        float f0 = sigf(xf + g0f);
        float f1 = sigf(xf + g1f);
        int c0 = children[2 * t], c1 = children[2 * t + 1];
        float cc = i * u + f0 * g_c[c0 * HD + j] + f1 * g_c[c1 * HD + j];
        g_c[t * HD + j] = cc;
        g_h[t * HD + j] = o * tanhf_fast(cc);
    }
}

// ---------------- persistent mega-kernel ----------------
__global__ __launch_bounds__(NTHR, 2) void mega_kernel(
    const int* __restrict__ word_ids, const int* __restrict__ labels,
    const int* __restrict__ children, const float* __restrict__ emb,
    const float* __restrict__ Wout, const float* __restrict__ bout,
    float* __restrict__ out, int out_size)
{
    __shared__ float As[2][32][68];
    __shared__ __align__(16) float Bs[2][32][64];
    __shared__ float sred[NTHR];

    unsigned barno = 0;

    // ---- stage 1: prologue GEMM  XX = emb[word_ids] @ Wxp ----
    gemm_stage(emb, word_ids, NN, g_Wxp, g_XX, 1, 0, As, Bs);
    gbar(++barno);

    // ---- stage 2: leaves ----
    for (int idx = blockIdx.x * NTHR + threadIdx.x; idx < NLEAVES * HD; idx += NBLK * NTHR) {
        int t = idx / HD, j = idx % HD;
        const float* xx = g_XX + (size_t)t * NBP;
        float i = sigf(xx[j]          + g_bsum[j]);
        float o = sigf(xx[GP + j]     + g_bsum[GP + j]);
        float u = sigf(xx[2 * GP + j] + g_bsum[2 * GP + j]);
        float c = i * u;
        g_c[t * HD + j] = c;
        g_h[t * HD + j] = o * tanhf_fast(c);
    }
    gbar(++barno);

    // ---- stage 3: 9 sequential levels (split-K GEMM + unrolled epilogue) ----
    const int bases[9]  = {512, 768, 896, 960, 992, 1008, 1016, 1020, 1022};
    const int widths[9] = {256, 128, 64, 32, 16, 8, 4, 2, 1};
    const int splits[9] = {2, 4, 5, 10, 10, 10, 10, 10, 10};
#pragma unroll 1
    for (int l = 0; l < 9; l++) {
        const int W = widths[l], base = bases[l], sp = splits[l];
        gemm_stage(g_h, children + 2 * base, 2 * W, g_Whp, g_Gs, sp, GSTRIDE, As, Bs);
        gbar(++barno);
        switch (sp) {
            case 2:  level_epi<2>(base, W, children);  break;
            case 4:  level_epi<4>(base, W, children);  break;
            case 5:  level_epi<5>(base, W, children);  break;
            default: level_epi<10>(base, W, children); break;
        }
        gbar(++barno);
    }

    // ---- stage 4: logits + log_softmax + per-node loss (warp per node) ----
    {
        int gw = (blockIdx.x * NTHR + threadIdx.x) >> 5;
        int lane = threadIdx.x & 31;
        if (gw < NN) {
            const float* h = g_h + (size_t)gw * HD;
            float a0 = 0.f, a1 = 0.f, a2 = 0.f, a3 = 0.f, a4 = 0.f;
            for (int j = lane; j < HD; j += 32) {
                float hv = h[j];
                const float* w = Wout + j * 5;
                a0 += hv * w[0]; a1 += hv * w[1]; a2 += hv * w[2];
                a3 += hv * w[3]; a4 += hv * w[4];
            }
#pragma unroll
            for (int off = 16; off > 0; off >>= 1) {
                a0 += __shfl_down_sync(0xffffffffu, a0, off);
                a1 += __shfl_down_sync(0xffffffffu, a1, off);
                a2 += __shfl_down_sync(0xffffffffu, a2, off);
                a3 += __shfl_down_sync(0xffffffffu, a3, off);
                a4 += __shfl_down_sync(0xffffffffu, a4, off);
            }
            if (lane == 0) {
                float lg[5] = {a0 + bout[0], a1 + bout[1], a2 + bout[2],
                               a3 + bout[3], a4 + bout[4]};
                float mx = lg[0];
#pragma unroll
                for (int l = 1; l < 5; l++) mx = fmaxf(mx, lg[l]);
                float se = 0.f;
#pragma unroll
                for (int l = 0; l < 5; l++) se += __expf(lg[l] - mx);
                float lse = mx + __logf(se);
                float* dst = (out_size >= NN * 5) ? (out + (size_t)gw * 5)
                                                  : (g_logp_scratch + (size_t)gw * 5);
#pragma unroll
                for (int l = 0; l < 5; l++) dst[l] = lg[l] - lse;
                g_loss[gw] = -(lg[labels[gw]] - lse);
            }
        }
    }

    // ---- final barrier: arrival-only; block 0 reduces loss and resets state ----
    {
        const unsigned fin = ++barno;
        __syncthreads();
        if (threadIdx.x == 0) {
            __threadfence();
            atomicAdd(&g_cnt[(blockIdx.x & (NSHARD - 1)) << 5], 1u);
        }
        if (blockIdx.x != 0) return;

        if (threadIdx.x < NSHARD) {
            const unsigned want = SHBLK * fin;
            while (*((volatile unsigned*)&g_cnt[threadIdx.x << 5]) < want) { }
        }
        __syncthreads();
        if (threadIdx.x == 0) __threadfence();   // acquire: fresh g_loss
        __syncthreads();

        float v = 0.f;
        for (int i = threadIdx.x; i < NN; i += NTHR) v += g_loss[i];
        sred[threadIdx.x] = v;
        __syncthreads();
        for (int st = NTHR / 2; st > 0; st >>= 1) {
            if (threadIdx.x < st) sred[threadIdx.x] += sred[threadIdx.x + st];
            __syncthreads();
        }
        if (threadIdx.x == 0) {
            if (out_size > NN * 5)      out[NN * 5] = sred[0];
            else if (out_size < NN * 5) out[0]      = sred[0];
        }
        __syncthreads();

        // reset barrier state for the next graph replay
        if (threadIdx.x < NSHARD)
            *((volatile unsigned*)&g_cnt[threadIdx.x << 5]) = 0;
        if (threadIdx.x == 0) __threadfence();
    }
}

// ---------------- launch ----------------
extern "C" void kernel_launch(void* const* d_in, const int* in_sizes, int n_in,
                              void* d_out, int out_size)
{
    const int*   word_ids = (const int*)d_in[0];
    const int*   labels   = (const int*)d_in[1];
    const int*   children = (const int*)d_in[2];
    const float* emb = (const float*)d_in[4];
    const float* Wix = (const float*)d_in[5],  *bix = (const float*)d_in[6];
    const float* Wih = (const float*)d_in[7],  *bih = (const float*)d_in[8];
    const float* Wfx = (const float*)d_in[9],  *bfx = (const float*)d_in[10];
    const float* Wfh = (const float*)d_in[11], *bfh = (const float*)d_in[12];
    const float* Wux = (const float*)d_in[13], *bux = (const float*)d_in[14];
    const float* Wuh = (const float*)d_in[15], *buh = (const float*)d_in[16];
    const float* Wout = (const float*)d_in[17], *bout = (const float*)d_in[18];
    float* out = (float*)d_out;

    pack_w<<<(HD * NBP + 255) / 256, 256>>>(Wix, Wfx, Wux, Wih, Wfh, Wuh,
                                            bix, bfx, bux, bih, bfh, buh);
    mega_kernel<<<NBLK, NTHR>>>(word_ids, labels, children, emb, Wout, bout,
                                out, out_size);
}